// round 1
// baseline (speedup 1.0000x reference)
#include <cuda_runtime.h>
#include <math.h>

#define BB   128
#define TT   24
#define EE   512
#define HH   512
#define VV   10000
#define G4   2048           // 4*H
#define BTR  3072           // B*T rows, r = t*128 + b
#define OUTROW 250000       // (T+1)*V

// -------- device scratch (no allocations allowed) --------
__device__ float g_X [BTR * EE];         // embedded captions, [r, E]
__device__ float g_Xg[BTR * G4];         // X @ W_ih^T + (b_ih + b_hh)
__device__ float g_Hall[BTR * HH];       // all hidden states
__device__ float g_hA[BB * HH];
__device__ float g_hB[BB * HH];
__device__ float g_c [BB * HH];
__device__ float g_bias[G4];

__device__ __forceinline__ float sigf(float x) { return 1.0f / (1.0f + expf(-x)); }

// -------- init: h0 = images, c0 = 0, bias = b_ih + b_hh --------
__global__ void k_init(const float* __restrict__ img,
                       const float* __restrict__ bih,
                       const float* __restrict__ bhh) {
    int i = blockIdx.x * blockDim.x + threadIdx.x;
    if (i < BB * HH) { g_hA[i] = img[i]; g_c[i] = 0.0f; }
    if (i < G4)      { g_bias[i] = bih[i] + bhh[i]; }
}

// -------- embedding gather with padding_idx = 0 --------
__global__ void k_embed(const int* __restrict__ caps,
                        const float* __restrict__ Wemb) {
    int idx = blockIdx.x * blockDim.x + threadIdx.x;   // over BTR*EE/4 float4s
    const int n4 = BTR * (EE / 4);
    if (idx >= n4) return;
    int e4 = idx & (EE / 4 - 1);       // 0..127
    int r  = idx >> 7;                 // row: r = t*128 + b
    int t  = r >> 7;
    int b  = r & 127;
    int tok = caps[b * TT + t];
    float4 v = make_float4(0.f, 0.f, 0.f, 0.f);
    if (tok != 0)
        v = *(const float4*)(Wemb + (size_t)tok * EE + e4 * 4);
    *(float4*)(g_X + (size_t)r * EE + e4 * 4) = v;
}

// -------- generic NT SGEMM: C[m,n] = sum_k A[m,k]*Bm[n,k] + bias[n] --------
// Tile 128x128, BK=16, 256 threads, 8x8 microtile.
// mode 0: plain store C[m*N+n]
// mode 1: store into captioning output: m = t*128+b -> out[b*OUTROW + (t+1)*V + n]
__global__ void sgemm128(const float* __restrict__ A,
                         const float* __restrict__ Bm,
                         const float* __restrict__ bias,
                         float* __restrict__ Cout,
                         int M, int N, int K, int mode) {
    __shared__ float As[16][132];
    __shared__ float Bs[16][132];

    const int bm  = blockIdx.y * 128;
    const int bn  = blockIdx.x * 128;
    const int tid = threadIdx.x;
    const int tr  = (tid >> 4) * 8;    // 0..120
    const int tc  = (tid & 15) * 8;    // 0..120

    float acc[8][8];
#pragma unroll
    for (int i = 0; i < 8; i++)
#pragma unroll
        for (int j = 0; j < 8; j++) acc[i][j] = 0.0f;

    for (int k0 = 0; k0 < K; k0 += 16) {
        // load A tile (128 x 16): 512 float4, 2 per thread
#pragma unroll
        for (int i = 0; i < 2; i++) {
            int f4  = tid + i * 256;
            int row = f4 >> 2;
            int kq  = (f4 & 3) * 4;
            float4 v = *(const float4*)(A + (size_t)(bm + row) * K + k0 + kq);
            As[kq + 0][row] = v.x; As[kq + 1][row] = v.y;
            As[kq + 2][row] = v.z; As[kq + 3][row] = v.w;
        }
        // load B tile (128 x 16), rows may exceed N
#pragma unroll
        for (int i = 0; i < 2; i++) {
            int f4  = tid + i * 256;
            int row = f4 >> 2;
            int kq  = (f4 & 3) * 4;
            int gn  = bn + row;
            float4 v = make_float4(0.f, 0.f, 0.f, 0.f);
            if (gn < N)
                v = *(const float4*)(Bm + (size_t)gn * K + k0 + kq);
            Bs[kq + 0][row] = v.x; Bs[kq + 1][row] = v.y;
            Bs[kq + 2][row] = v.z; Bs[kq + 3][row] = v.w;
        }
        __syncthreads();

#pragma unroll
        for (int k = 0; k < 16; k++) {
            float a[8], b[8];
            *(float4*)&a[0] = *(const float4*)&As[k][tr];
            *(float4*)&a[4] = *(const float4*)&As[k][tr + 4];
            *(float4*)&b[0] = *(const float4*)&Bs[k][tc];
            *(float4*)&b[4] = *(const float4*)&Bs[k][tc + 4];
#pragma unroll
            for (int i = 0; i < 8; i++)
#pragma unroll
                for (int j = 0; j < 8; j++)
                    acc[i][j] += a[i] * b[j];
        }
        __syncthreads();
    }

#pragma unroll
    for (int i = 0; i < 8; i++) {
        int m = bm + tr + i;
#pragma unroll
        for (int j = 0; j < 8; j++) {
            int n = bn + tc + j;
            if (n < N) {
                float v = acc[i][j] + (bias ? bias[n] : 0.0f);
                if (mode == 0) {
                    Cout[(size_t)m * N + n] = v;
                } else {
                    int t = m >> 7;
                    int b = m & 127;
                    Cout[(size_t)b * OUTROW + (size_t)(t + 1) * VV + n] = v;
                }
            }
        }
    }
}

// -------- fused LSTM step: gates = Xg[t] + h@W_hh^T ; cell update --------
// grid: (16 j-tiles of 32, 8 b-tiles of 16), 128 threads.
// Each block computes [16 b x 32 j x 4 gates]; thread: 4 b x 1 j x 4 gates.
__global__ void lstm_step(const float* __restrict__ hin,
                          float* __restrict__ hout,
                          const float* __restrict__ Whh,
                          int t) {
    __shared__ float Ws[128][37];   // row = g*32 + jl, cols = k chunk
    __shared__ float hs[16][37];

    const int tid = threadIdx.x;
    const int jl  = tid & 31;
    const int bq  = tid >> 5;           // 0..3 (warp id)
    const int j0  = blockIdx.x * 32;
    const int b0  = blockIdx.y * 16;

    float acc[4][4];                    // [b][gate]
#pragma unroll
    for (int i = 0; i < 4; i++)
#pragma unroll
        for (int g = 0; g < 4; g++) acc[i][g] = 0.0f;

    for (int k0 = 0; k0 < HH; k0 += 32) {
        // load W chunk: 128 rows x 32 k = 1024 float4, 8 per thread
#pragma unroll
        for (int i = 0; i < 8; i++) {
            int f4  = tid + i * 128;
            int row = f4 >> 3;          // 0..127
            int kq  = (f4 & 7) * 4;
            int g   = row >> 5;
            int jj  = row & 31;
            float4 v = *(const float4*)(Whh + (size_t)(g * 512 + j0 + jj) * HH + k0 + kq);
            Ws[row][kq + 0] = v.x; Ws[row][kq + 1] = v.y;
            Ws[row][kq + 2] = v.z; Ws[row][kq + 3] = v.w;
        }
        // load h chunk: 16 rows x 32 k = 128 float4, 1 per thread
        {
            int row = tid >> 3;
            int kq  = (tid & 7) * 4;
            float4 v = *(const float4*)(hin + (size_t)(b0 + row) * HH + k0 + kq);
            hs[row][kq + 0] = v.x; hs[row][kq + 1] = v.y;
            hs[row][kq + 2] = v.z; hs[row][kq + 3] = v.w;
        }
        __syncthreads();

#pragma unroll
        for (int k = 0; k < 32; k++) {
            float a0 = hs[bq * 4 + 0][k];
            float a1 = hs[bq * 4 + 1][k];
            float a2 = hs[bq * 4 + 2][k];
            float a3 = hs[bq * 4 + 3][k];
            float w0 = Ws[jl      ][k];
            float w1 = Ws[32 + jl ][k];
            float w2 = Ws[64 + jl ][k];
            float w3 = Ws[96 + jl ][k];
            acc[0][0] += a0 * w0; acc[0][1] += a0 * w1; acc[0][2] += a0 * w2; acc[0][3] += a0 * w3;
            acc[1][0] += a1 * w0; acc[1][1] += a1 * w1; acc[1][2] += a1 * w2; acc[1][3] += a1 * w3;
            acc[2][0] += a2 * w0; acc[2][1] += a2 * w1; acc[2][2] += a2 * w2; acc[2][3] += a2 * w3;
            acc[3][0] += a3 * w0; acc[3][1] += a3 * w1; acc[3][2] += a3 * w2; acc[3][3] += a3 * w3;
        }
        __syncthreads();
    }

    // cell epilogue: this thread owns (b0+bq*4+i, j0+jl) for all 4 gates
    const int j = j0 + jl;
#pragma unroll
    for (int i = 0; i < 4; i++) {
        int b = b0 + bq * 4 + i;
        int r = t * 128 + b;
        const float* xg = g_Xg + (size_t)r * G4 + j;
        float iv = acc[i][0] + xg[0];
        float fv = acc[i][1] + xg[512];
        float gv = acc[i][2] + xg[1024];
        float ov = acc[i][3] + xg[1536];
        float cO = g_c[b * HH + j];
        float cN = sigf(fv) * cO + sigf(iv) * tanhf(gv);
        float hN = sigf(ov) * tanhf(cN);
        g_c[b * HH + j] = cN;
        hout[b * HH + j] = hN;
        g_Hall[(size_t)r * HH + j] = hN;
    }
}

// -------- t=0 one-hot rows + optional length tail --------
__global__ void k_start(float* __restrict__ out,
                        const int* __restrict__ clen, int extra) {
    int i = blockIdx.x * blockDim.x + threadIdx.x;
    const int n = BB * VV;
    if (i < n) {
        int b = i / VV;
        int v = i - b * VV;
        out[(size_t)b * OUTROW + v] = (v == 1) ? 1.0f : 0.0f;
    }
    if (i < extra) {
        float val = (i < BB) ? (float)(clen[i] - 1) : 0.0f;
        out[(size_t)BB * OUTROW + i] = val;
    }
}

extern "C" void kernel_launch(void* const* d_in, const int* in_sizes, int n_in,
                              void* d_out, int out_size) {
    const float* images = (const float*)d_in[0];
    const int*   caps   = (const int*)  d_in[1];
    const int*   clen   = (const int*)  d_in[2];
    const float* Wemb   = (const float*)d_in[3];
    const float* Wih    = (const float*)d_in[4];
    const float* Whh    = (const float*)d_in[5];
    const float* bih    = (const float*)d_in[6];
    const float* bhh    = (const float*)d_in[7];
    const float* Wout   = (const float*)d_in[8];
    const float* bout   = (const float*)d_in[9];
    float* out = (float*)d_out;

    float *pX, *pXg, *pH, *phA, *phB, *pbias;
    cudaGetSymbolAddress((void**)&pX,    g_X);
    cudaGetSymbolAddress((void**)&pXg,   g_Xg);
    cudaGetSymbolAddress((void**)&pH,    g_Hall);
    cudaGetSymbolAddress((void**)&phA,   g_hA);
    cudaGetSymbolAddress((void**)&phB,   g_hB);
    cudaGetSymbolAddress((void**)&pbias, g_bias);

    // 1. init h0 = images, c0 = 0, combined bias
    k_init<<<(BB * HH + 255) / 256, 256>>>(images, bih, bhh);

    // 2. embedding
    k_embed<<<(BTR * EE / 4 + 255) / 256, 256>>>(caps, Wemb);

    // 3. Xg = X @ W_ih^T + bias   [3072 x 2048]
    {
        dim3 grid(G4 / 128, BTR / 128);
        sgemm128<<<grid, 256>>>(pX, Wih, pbias, pXg, BTR, G4, EE, 0);
    }

    // 4. recurrence: 24 fused GEMM+cell steps, double-buffered h
    {
        dim3 grid(HH / 32, BB / 16);
        for (int t = 0; t < TT; t++) {
            const float* hin = (t & 1) ? phB : phA;
            float*       ho  = (t & 1) ? phA : phB;
            lstm_step<<<grid, 128>>>(hin, ho, Whh, t);
        }
    }

    // 5. logits = H_all @ W_out^T + b_out  -> scattered into d_out
    {
        dim3 grid((VV + 127) / 128, BTR / 128);
        sgemm128<<<grid, 256>>>(pH, Wout, bout, out, BTR, VV, HH, 1);
    }

    // 6. t=0 one-hot rows, plus (captions_length - 1) tail if present
    {
        int extra = out_size - BB * OUTROW;
        if (extra < 0) extra = 0;
        int nthreads = BB * VV;
        k_start<<<(nthreads + 255) / 256, 256>>>(out, clen, extra);
    }
}